// round 1
// baseline (speedup 1.0000x reference)
#include <cuda_runtime.h>
#include <math.h>

// ---------------- problem constants ----------------
constexpr int B = 512, T = 64, S = 128, A = 32, H = 1024, R = 1024;
constexpr int KP = S + A;     // 160   concat(state, action)
constexpr int N3 = 3 * R;     // 3072  GRU gate width
constexpr int NO = 2 * S;     // 256   [mean | raw_std]
constexpr int SK = 4;         // split-K for the small output GEMM

// output layout: means, stds, states [B,T,S]; beliefs, prev_beliefs [B,T,R]
constexpr size_t OFF_MEAN  = 0;
constexpr size_t OFF_STD   = OFF_MEAN  + (size_t)B * T * S;
constexpr size_t OFF_STATE = OFF_STD   + (size_t)B * T * S;
constexpr size_t OFF_BEL   = OFF_STATE + (size_t)B * T * S;
constexpr size_t OFF_PREV  = OFF_BEL   + (size_t)B * T * R;

// ---------------- device scratch (static, no runtime alloc) ----------------
__device__ float g_xa[B * KP];       // concat(state, action_t)
__device__ float g_x [B * H];        // elu(proj)
__device__ float g_gi[B * N3];       // x @ W_ih + b_ih
__device__ float g_gh[B * N3];       // belief @ W_hh + b_hh
__device__ float g_h [B * H];        // elu(belief @ W_h1 + b_h1)
__device__ float g_belief[B * R];    // recurrent belief
__device__ float g_state [B * S];    // recurrent state
__device__ float g_msp[SK * B * NO]; // split-K partials of out GEMM

// ---------------- init: load recurrent state ----------------
__global__ void init_k(const float* __restrict__ prior_state,
                       const float* __restrict__ belief0) {
    int idx = blockIdx.x * blockDim.x + threadIdx.x;
    if (idx < B * R) g_belief[idx] = belief0[idx];
    if (idx < B * S) g_state[idx]  = prior_state[idx];
}

// ---------------- pack: g_xa = [state | action_t] ----------------
__global__ void pack_k(const float* __restrict__ actions, int t) {
    int idx = blockIdx.x * blockDim.x + threadIdx.x;
    if (idx >= B * KP) return;
    int b = idx / KP, j = idx % KP;
    g_xa[idx] = (j < S) ? g_state[b * S + j]
                        : actions[(size_t)b * T * A + (size_t)t * A + (j - S)];
}

// ---------------- generic tiled fp32 GEMM ----------------
// C[M,N] = A[M,K] @ W[K,N] (+bias, +elu), row-major everywhere.
// EPI: 0 = store(acc+bias), 1 = store(elu(acc+bias)), 3 = split-K partial store
// DUAL: blockIdx.z==1 selects the second (A,W,bias,C) set (gi/gh fusion)
template<int BM, int BN, int BK, int TM, int TN, int EPI, int DUAL, int SPLITK>
__global__ void __launch_bounds__((BM / TM) * (BN / TN))
gemm_k(const float* __restrict__ A0, const float* __restrict__ W0,
       const float* __restrict__ b0, float* __restrict__ C0,
       const float* __restrict__ A1, const float* __restrict__ W1,
       const float* __restrict__ b1, float* __restrict__ C1,
       int M, int N, int K) {
    constexpr int THREADS = (BM / TM) * (BN / TN);
    constexpr int PAD = 4;

    const float* Am = A0; const float* Wm = W0; const float* bias = b0;
    float* Cm = C0;
    if (DUAL && blockIdx.z == 1) { Am = A1; Wm = W1; bias = b1; Cm = C1; }

    int kz0 = 0, kz1 = K;
    if (SPLITK > 1) {
        int kc = K / SPLITK;
        kz0 = blockIdx.z * kc; kz1 = kz0 + kc;
    }

    __shared__ float As[BK][BM + PAD];
    __shared__ float Bs[BK][BN + PAD];

    const int tid = threadIdx.x;
    const int m0 = blockIdx.y * BM;
    const int n0 = blockIdx.x * BN;
    const int ty = tid / (BN / TN);
    const int tx = tid % (BN / TN);

    float acc[TM][TN] = {};

    constexpr int LA4 = (BM * BK) / (THREADS * 4);  // float4 loads of A per thread
    constexpr int LB4 = (BK * BN) / (THREADS * 4);  // float4 loads of W per thread

    for (int kt = kz0; kt < kz1; kt += BK) {
        #pragma unroll
        for (int i = 0; i < LA4; i++) {
            int idx = (tid + i * THREADS) * 4;       // flat (m,k) in A tile
            int m = idx / BK, k = idx % BK;
            float4 v = *(const float4*)&Am[(size_t)(m0 + m) * K + kt + k];
            As[k + 0][m] = v.x; As[k + 1][m] = v.y;
            As[k + 2][m] = v.z; As[k + 3][m] = v.w;
        }
        #pragma unroll
        for (int i = 0; i < LB4; i++) {
            int idx = (tid + i * THREADS) * 4;       // flat (k,n) in W tile
            int k = idx / BN, n = idx % BN;
            *(float4*)&Bs[k][n] = *(const float4*)&Wm[(size_t)(kt + k) * N + n0 + n];
        }
        __syncthreads();

        #pragma unroll
        for (int kk = 0; kk < BK; kk++) {
            float a[TM], b[TN];
            #pragma unroll
            for (int i = 0; i < TM; i += 4)
                *(float4*)&a[i] = *(const float4*)&As[kk][ty * TM + i];
            #pragma unroll
            for (int j = 0; j < TN; j += 4)
                *(float4*)&b[j] = *(const float4*)&Bs[kk][tx * TN + j];
            #pragma unroll
            for (int i = 0; i < TM; i++)
                #pragma unroll
                for (int j = 0; j < TN; j++)
                    acc[i][j] = fmaf(a[i], b[j], acc[i][j]);
        }
        __syncthreads();
    }

    // epilogue
    if constexpr (EPI == 3) {
        float* Cz = Cm + (size_t)blockIdx.z * M * N;
        #pragma unroll
        for (int i = 0; i < TM; i++) {
            int m = m0 + ty * TM + i;
            #pragma unroll
            for (int j = 0; j < TN; j++)
                Cz[(size_t)m * N + n0 + tx * TN + j] = acc[i][j];
        }
    } else {
        #pragma unroll
        for (int i = 0; i < TM; i++) {
            int m = m0 + ty * TM + i;
            #pragma unroll
            for (int j = 0; j < TN; j++) {
                int n = n0 + tx * TN + j;
                float v = acc[i][j] + bias[n];
                if constexpr (EPI == 1) v = (v > 0.f) ? v : expm1f(v);
                Cm[(size_t)m * N + n] = v;
            }
        }
    }
}

// ---------------- GRU gate + belief update ----------------
__global__ void gate_k(float* __restrict__ out, int t) {
    int idx = blockIdx.x * blockDim.x + threadIdx.x;
    if (idx >= B * R) return;
    int b = idx / R, r = idx % R;
    size_t base = (size_t)b * N3;
    float ir = g_gi[base + r],     hr = g_gh[base + r];
    float iz = g_gi[base + R + r], hz = g_gh[base + R + r];
    float in_ = g_gi[base + 2 * R + r], hn = g_gh[base + 2 * R + r];
    float rg = 1.f / (1.f + expf(-(ir + hr)));
    float zg = 1.f / (1.f + expf(-(iz + hz)));
    float ng = tanhf(in_ + rg * hn);
    float old = g_belief[idx];
    float nb = (1.f - zg) * ng + zg * old;
    g_belief[idx] = nb;
    size_t o = (size_t)b * T * R + (size_t)t * R + r;
    out[OFF_BEL + o]  = nb;
    out[OFF_PREV + o] = old;
}

// ---------------- epilogue: softplus/std, reparam sample, outputs ----------------
__global__ void epi_k(const float* __restrict__ noise,
                      const float* __restrict__ b_out,
                      float* __restrict__ out, int t) {
    int idx = blockIdx.x * blockDim.x + threadIdx.x;
    if (idx >= B * S) return;
    int b = idx / S, s = idx % S;
    float mean = b_out[s];
    float raw  = b_out[S + s];
    #pragma unroll
    for (int z = 0; z < SK; z++) {
        mean += g_msp[(size_t)z * B * NO + (size_t)b * NO + s];
        raw  += g_msp[(size_t)z * B * NO + (size_t)b * NO + S + s];
    }
    float sp  = fmaxf(raw, 0.f) + log1pf(expf(-fabsf(raw)));  // stable softplus
    float std = sp + 0.1f;
    float eps = noise[(size_t)b * T * S + (size_t)t * S + s];
    float st  = fmaf(std, eps, mean);
    size_t o = (size_t)b * T * S + (size_t)t * S + s;
    out[OFF_MEAN + o]  = mean;
    out[OFF_STD + o]   = std;
    out[OFF_STATE + o] = st;
    g_state[idx] = st;
}

// ---------------- launch ----------------
extern "C" void kernel_launch(void* const* d_in, const int* in_sizes, int n_in,
                              void* d_out, int out_size) {
    const float* prior_state = (const float*)d_in[0];
    const float* belief0     = (const float*)d_in[1];
    const float* actions     = (const float*)d_in[2];
    const float* noise       = (const float*)d_in[3];
    const float* W_proj = (const float*)d_in[4];
    const float* b_proj = (const float*)d_in[5];
    const float* W_ih   = (const float*)d_in[6];
    const float* b_ih   = (const float*)d_in[7];
    const float* W_hh   = (const float*)d_in[8];
    const float* b_hh   = (const float*)d_in[9];
    const float* W_h1   = (const float*)d_in[10];
    const float* b_h1   = (const float*)d_in[11];
    const float* W_out  = (const float*)d_in[12];
    const float* b_out  = (const float*)d_in[13];
    float* out = (float*)d_out;

    float *p_xa, *p_x, *p_gi, *p_gh, *p_h, *p_bel, *p_msp;
    cudaGetSymbolAddress((void**)&p_xa,  g_xa);
    cudaGetSymbolAddress((void**)&p_x,   g_x);
    cudaGetSymbolAddress((void**)&p_gi,  g_gi);
    cudaGetSymbolAddress((void**)&p_gh,  g_gh);
    cudaGetSymbolAddress((void**)&p_h,   g_h);
    cudaGetSymbolAddress((void**)&p_bel, g_belief);
    cudaGetSymbolAddress((void**)&p_msp, g_msp);

    init_k<<<(B * R + 255) / 256, 256>>>(prior_state, belief0);

    for (int t = 0; t < T; t++) {
        // x_t = elu([state | action_t] @ W_proj + b_proj)
        pack_k<<<(B * KP + 255) / 256, 256>>>(actions, t);
        gemm_k<64, 128, 16, 8, 8, /*EPI*/1, /*DUAL*/0, /*SK*/1>
            <<<dim3(H / 128, B / 64, 1), 128>>>(
                p_xa, W_proj, b_proj, p_x,
                nullptr, nullptr, nullptr, nullptr, B, H, KP);

        // gi = x @ W_ih + b_ih ; gh = belief @ W_hh + b_hh (fused via z)
        gemm_k<64, 128, 16, 8, 8, /*EPI*/0, /*DUAL*/1, /*SK*/1>
            <<<dim3(N3 / 128, B / 64, 2), 128>>>(
                p_x, W_ih, b_ih, p_gi,
                p_bel, W_hh, b_hh, p_gh, B, N3, H);

        // GRU gates -> new belief, write beliefs + prev_beliefs
        gate_k<<<(B * R + 255) / 256, 256>>>(out, t);

        // h = elu(belief @ W_h1 + b_h1)
        gemm_k<64, 128, 16, 8, 8, /*EPI*/1, /*DUAL*/0, /*SK*/1>
            <<<dim3(H / 128, B / 64, 1), 128>>>(
                p_bel, W_h1, b_h1, p_h,
                nullptr, nullptr, nullptr, nullptr, B, H, R);

        // [mean | raw_std] = h @ W_out (split-K partials, deterministic)
        gemm_k<64, 64, 16, 8, 8, /*EPI*/3, /*DUAL*/0, /*SK*/SK>
            <<<dim3(NO / 64, B / 64, SK), 64>>>(
                p_h, W_out, nullptr, p_msp,
                nullptr, nullptr, nullptr, nullptr, B, NO, R);

        // std/softplus, reparam sample, write means/stds/states
        epi_k<<<(B * S + 255) / 256, 256>>>(noise, b_out, out, t);
    }
}

// round 3
// speedup vs baseline: 1.8556x; 1.8556x over previous
#include <cuda_runtime.h>
#include <cuda_bf16.h>
#include <math.h>
#include <stdint.h>

// ---------------- problem constants ----------------
constexpr int B = 512, T = 64, S = 128, A = 32, H = 1024, R = 1024;
constexpr int KP = S + A;     // 160
constexpr int N3 = 3 * R;     // 3072
constexpr int NO = 2 * S;     // 256
constexpr int SK = 4;

constexpr size_t OFF_MEAN  = 0;
constexpr size_t OFF_STD   = OFF_MEAN  + (size_t)B * T * S;
constexpr size_t OFF_STATE = OFF_STD   + (size_t)B * T * S;
constexpr size_t OFF_BEL   = OFF_STATE + (size_t)B * T * S;
constexpr size_t OFF_PREV  = OFF_BEL   + (size_t)B * T * R;

// ---------------- device scratch ----------------
__device__ float g_xa[B * KP];
__device__ float g_gi[B * N3];
__device__ float g_gh[B * N3];
__device__ float g_h [B * H];
__device__ float g_belief[B * R];
__device__ float g_state [B * S];
__device__ float g_msp[SK * B * NO];

// bf16 split activations
__device__ __nv_bfloat16 g_x_hi[B * H],   g_x_lo[B * H];
__device__ __nv_bfloat16 g_bel_hi[B * R], g_bel_lo[B * R];
// bf16 split transposed weights  [N][K]
__device__ __nv_bfloat16 g_Wih_hi[N3 * H], g_Wih_lo[N3 * H];
__device__ __nv_bfloat16 g_Whh_hi[N3 * R], g_Whh_lo[N3 * R];
__device__ __nv_bfloat16 g_Wh1_hi[H * R],  g_Wh1_lo[H * R];

// ---------------- portable PTX helpers (sm_80+ features only) ----------------
__device__ __forceinline__ uint32_t smem_to_u32(const void* p) {
    uint32_t a;
    asm("{ .reg .u64 t; cvta.to.shared.u64 t, %1; cvt.u32.u64 %0, t; }" : "=r"(a) : "l"(p));
    return a;
}
__device__ __forceinline__ void cp16(uint32_t saddr, const void* gaddr) {
    asm volatile("cp.async.cg.shared.global [%0], [%1], 16;" :: "r"(saddr), "l"(gaddr) : "memory");
}
__device__ __forceinline__ void cp_commit() { asm volatile("cp.async.commit_group;" ::: "memory"); }
__device__ __forceinline__ void cp_wait1()  { asm volatile("cp.async.wait_group 1;" ::: "memory"); }
__device__ __forceinline__ void cp_wait0()  { asm volatile("cp.async.wait_group 0;" ::: "memory"); }

__device__ __forceinline__ void ldsm4(uint32_t a, uint32_t& r0, uint32_t& r1,
                                      uint32_t& r2, uint32_t& r3) {
    asm volatile("ldmatrix.sync.aligned.m8n8.x4.shared.b16 {%0,%1,%2,%3}, [%4];"
                 : "=r"(r0), "=r"(r1), "=r"(r2), "=r"(r3) : "r"(a));
}
__device__ __forceinline__ void mma_bf16(float* c, const uint32_t* a, const uint32_t* b) {
    asm volatile("mma.sync.aligned.m16n8k16.row.col.f32.bf16.bf16.f32 "
                 "{%0,%1,%2,%3},{%4,%5,%6,%7},{%8,%9},{%0,%1,%2,%3};"
                 : "+f"(c[0]), "+f"(c[1]), "+f"(c[2]), "+f"(c[3])
                 : "r"(a[0]), "r"(a[1]), "r"(a[2]), "r"(a[3]), "r"(b[0]), "r"(b[1]));
}

// ---------------- init ----------------
__global__ void init_k(const float* __restrict__ prior_state,
                       const float* __restrict__ belief0) {
    int idx = blockIdx.x * blockDim.x + threadIdx.x;
    if (idx < B * R) {
        float v = belief0[idx];
        g_belief[idx] = v;
        __nv_bfloat16 h = __float2bfloat16(v);
        g_bel_hi[idx] = h;
        g_bel_lo[idx] = __float2bfloat16(v - __bfloat162float(h));
    }
    if (idx < B * S) g_state[idx] = prior_state[idx];
}

// ---------------- weight prep: W[K][N] -> hi/lo[N][K] ----------------
__global__ void prep_w(const float* __restrict__ W, __nv_bfloat16* __restrict__ hi,
                       __nv_bfloat16* __restrict__ lo, int K, int N) {
    int idx = blockIdx.x * blockDim.x + threadIdx.x;
    if (idx >= N * K) return;
    int n = idx / K, k = idx % K;
    float v = W[(size_t)k * N + n];
    __nv_bfloat16 h = __float2bfloat16(v);
    hi[idx] = h;
    lo[idx] = __float2bfloat16(v - __bfloat162float(h));
}

// ---------------- pack ----------------
__global__ void pack_k(const float* __restrict__ actions, int t) {
    int idx = blockIdx.x * blockDim.x + threadIdx.x;
    if (idx >= B * KP) return;
    int b = idx / KP, j = idx % KP;
    g_xa[idx] = (j < S) ? g_state[b * S + j]
                        : actions[(size_t)b * T * A + (size_t)t * A + (j - S)];
}

// ---------------- SIMT fp32 GEMM (small GEMMs) ----------------
// EPI: 2 = elu then bf16 hi/lo split store (C0=hi, C1=lo), 3 = split-K partials
template<int BM, int BN, int BK, int TM, int TN, int EPI, int SPLITK>
__global__ void __launch_bounds__((BM / TM) * (BN / TN))
gemm_k(const float* __restrict__ Am, const float* __restrict__ Wm,
       const float* __restrict__ bias, float* __restrict__ C0, float* __restrict__ C1,
       int M, int N, int K) {
    constexpr int THREADS = (BM / TM) * (BN / TN);
    constexpr int PAD = 4;
    int kz0 = 0, kz1 = K;
    if (SPLITK > 1) { int kc = K / SPLITK; kz0 = blockIdx.z * kc; kz1 = kz0 + kc; }

    __shared__ float As[BK][BM + PAD];
    __shared__ float Bs[BK][BN + PAD];
    const int tid = threadIdx.x;
    const int m0 = blockIdx.y * BM, n0 = blockIdx.x * BN;
    const int ty = tid / (BN / TN), tx = tid % (BN / TN);
    float acc[TM][TN] = {};
    constexpr int LA4 = (BM * BK) / (THREADS * 4);
    constexpr int LB4 = (BK * BN) / (THREADS * 4);

    for (int kt = kz0; kt < kz1; kt += BK) {
        #pragma unroll
        for (int i = 0; i < LA4; i++) {
            int idx = (tid + i * THREADS) * 4;
            int m = idx / BK, k = idx % BK;
            float4 v = *(const float4*)&Am[(size_t)(m0 + m) * K + kt + k];
            As[k + 0][m] = v.x; As[k + 1][m] = v.y; As[k + 2][m] = v.z; As[k + 3][m] = v.w;
        }
        #pragma unroll
        for (int i = 0; i < LB4; i++) {
            int idx = (tid + i * THREADS) * 4;
            int k = idx / BN, n = idx % BN;
            *(float4*)&Bs[k][n] = *(const float4*)&Wm[(size_t)(kt + k) * N + n0 + n];
        }
        __syncthreads();
        #pragma unroll
        for (int kk = 0; kk < BK; kk++) {
            float a[TM], b[TN];
            #pragma unroll
            for (int i = 0; i < TM; i += 4) *(float4*)&a[i] = *(const float4*)&As[kk][ty * TM + i];
            #pragma unroll
            for (int j = 0; j < TN; j += 4) *(float4*)&b[j] = *(const float4*)&Bs[kk][tx * TN + j];
            #pragma unroll
            for (int i = 0; i < TM; i++)
                #pragma unroll
                for (int j = 0; j < TN; j++) acc[i][j] = fmaf(a[i], b[j], acc[i][j]);
        }
        __syncthreads();
    }

    if constexpr (EPI == 3) {
        float* Cz = C0 + (size_t)blockIdx.z * M * N;
        #pragma unroll
        for (int i = 0; i < TM; i++) {
            int m = m0 + ty * TM + i;
            #pragma unroll
            for (int j = 0; j < TN; j++) Cz[(size_t)m * N + n0 + tx * TN + j] = acc[i][j];
        }
    } else if constexpr (EPI == 2) {
        __nv_bfloat16* Hi = reinterpret_cast<__nv_bfloat16*>(C0);
        __nv_bfloat16* Lo = reinterpret_cast<__nv_bfloat16*>(C1);
        #pragma unroll
        for (int i = 0; i < TM; i++) {
            int m = m0 + ty * TM + i;
            #pragma unroll
            for (int j = 0; j < TN; j++) {
                int n = n0 + tx * TN + j;
                float v = acc[i][j] + bias[n];
                v = (v > 0.f) ? v : expm1f(v);
                __nv_bfloat16 h = __float2bfloat16(v);
                Hi[(size_t)m * N + n] = h;
                Lo[(size_t)m * N + n] = __float2bfloat16(v - __bfloat162float(h));
            }
        }
    } else {
        #pragma unroll
        for (int i = 0; i < TM; i++) {
            int m = m0 + ty * TM + i;
            #pragma unroll
            for (int j = 0; j < TN; j++) {
                int n = n0 + tx * TN + j;
                float v = acc[i][j] + bias[n];
                if constexpr (EPI == 1) v = (v > 0.f) ? v : expm1f(v);
                C0[(size_t)m * N + n] = v;
            }
        }
    }
}

// ---------------- bf16-split tensor-core GEMM (mma.sync path) ----------------
// C[M, N] = A[M, K] @ B[N, K]^T, A/B as bf16 hi/lo, fp32 accum, 3-pass split.
// SMEM rows padded to 80B (stride 40 bf16) -> conflict-free ldmatrix.
template<int BM, int BN, int WRM, int WRN, int ELU, int DUAL>
__global__ void __launch_bounds__(WRM * WRN * 32, 1)
mma_gemm(const __nv_bfloat16* __restrict__ Ahi0, const __nv_bfloat16* __restrict__ Alo0,
         const __nv_bfloat16* __restrict__ Bhi0, const __nv_bfloat16* __restrict__ Blo0,
         const float* __restrict__ bias0, float* __restrict__ C0,
         const __nv_bfloat16* __restrict__ Ahi1, const __nv_bfloat16* __restrict__ Alo1,
         const __nv_bfloat16* __restrict__ Bhi1, const __nv_bfloat16* __restrict__ Blo1,
         const float* __restrict__ bias1, float* __restrict__ C1,
         int N, int K) {
    constexpr int THREADS = WRM * WRN * 32;
    constexpr int WTM = BM / WRM, WTN = BN / WRN;
    constexpr int MF = WTM / 16, NF = WTN / 8;
    constexpr int RS = 80;                         // smem row stride (bytes)
    constexpr uint32_t OFS_AH = 0;
    constexpr uint32_t OFS_AL = (uint32_t)BM * RS;
    constexpr uint32_t OFS_BH = 2u * BM * RS;
    constexpr uint32_t OFS_BL = 2u * BM * RS + (uint32_t)BN * RS;
    constexpr uint32_t BUFSZ  = 2u * (BM + BN) * RS;
    constexpr int PPT = (BM + BN) * 8 / THREADS;   // cp.async pieces per thread

    extern __shared__ char smem[];
    const uint32_t sb = smem_to_u32(smem);

    const int tid = threadIdx.x;
    const int wid = tid >> 5, lane = tid & 31;
    const int wm = wid / WRN, wn = wid % WRN;
    const int m0 = blockIdx.y * BM, n0 = blockIdx.x * BN;

    const __nv_bfloat16 *Ahi = Ahi0, *Alo = Alo0, *Bhi = Bhi0, *Blo = Blo0;
    const float* bias = bias0;
    float* C = C0;
    if (DUAL && blockIdx.z == 1) { Ahi = Ahi1; Alo = Alo1; Bhi = Bhi1; Blo = Blo1; bias = bias1; C = C1; }

    const __nv_bfloat16* s0 = Ahi + (size_t)m0 * K;
    const __nv_bfloat16* s1 = Alo + (size_t)m0 * K;
    const __nv_bfloat16* s2 = Bhi + (size_t)n0 * K;
    const __nv_bfloat16* s3 = Blo + (size_t)n0 * K;

    const int NC = K / 32;
    float acc[MF][NF][4];
    #pragma unroll
    for (int i = 0; i < MF; i++)
        #pragma unroll
        for (int j = 0; j < NF; j++)
            #pragma unroll
            for (int q = 0; q < 4; q++) acc[i][j][q] = 0.f;

    auto load_chunk = [&](int c, int buf) {
        uint32_t base = sb + (uint32_t)buf * BUFSZ;
        #pragma unroll
        for (int i = 0; i < PPT; i++) {
            int p = tid + i * THREADS;
            const __nv_bfloat16* s;
            uint32_t ofs;
            int local;
            if (p < BM * 4)                { s = s0; ofs = OFS_AH; local = p; }
            else if (p < 2 * BM * 4)       { s = s1; ofs = OFS_AL; local = p - BM * 4; }
            else if (p < 2 * BM * 4 + BN * 4) { s = s2; ofs = OFS_BH; local = p - 2 * BM * 4; }
            else                           { s = s3; ofs = OFS_BL; local = p - 2 * BM * 4 - BN * 4; }
            int row = local >> 2, k16 = local & 3;
            cp16(base + ofs + (uint32_t)row * RS + (uint32_t)k16 * 16,
                 s + (size_t)row * K + c * 32 + k16 * 8);
        }
    };

    auto mma_chunk = [&](int buf) {
        uint32_t base = sb + (uint32_t)buf * BUFSZ;
        const int grp = lane >> 3, l8 = lane & 7;
        #pragma unroll
        for (int ks = 0; ks < 2; ks++) {
            uint32_t ahi[MF][4], alo[MF][4], bhi[NF][2], blo[NF][2];
            uint32_t arow = (uint32_t)(wm * WTM + (grp & 1) * 8 + l8);
            uint32_t acol = (uint32_t)(ks * 32 + (grp >> 1) * 16);
            #pragma unroll
            for (int mt = 0; mt < MF; mt++) {
                uint32_t r = (arow + mt * 16) * RS + acol;
                ldsm4(base + OFS_AH + r, ahi[mt][0], ahi[mt][1], ahi[mt][2], ahi[mt][3]);
                ldsm4(base + OFS_AL + r, alo[mt][0], alo[mt][1], alo[mt][2], alo[mt][3]);
            }
            uint32_t brow = (uint32_t)(wn * WTN + (grp >> 1) * 8 + l8);
            uint32_t bcol = (uint32_t)(ks * 32 + (grp & 1) * 16);
            #pragma unroll
            for (int np = 0; np < NF / 2; np++) {
                uint32_t r = (brow + np * 16) * RS + bcol;
                ldsm4(base + OFS_BH + r, bhi[2 * np][0], bhi[2 * np][1],
                      bhi[2 * np + 1][0], bhi[2 * np + 1][1]);
                ldsm4(base + OFS_BL + r, blo[2 * np][0], blo[2 * np][1],
                      blo[2 * np + 1][0], blo[2 * np + 1][1]);
            }
            #pragma unroll
            for (int mt = 0; mt < MF; mt++)
                #pragma unroll
                for (int nt = 0; nt < NF; nt++) {
                    mma_bf16(acc[mt][nt], ahi[mt], bhi[nt]);
                    mma_bf16(acc[mt][nt], ahi[mt], blo[nt]);
                    mma_bf16(acc[mt][nt], alo[mt], bhi[nt]);
                }
        }
    };

    load_chunk(0, 0);
    cp_commit();
    for (int c = 0; c < NC; c++) {
        if (c + 1 < NC) { load_chunk(c + 1, (c + 1) & 1); cp_commit(); cp_wait1(); }
        else            { cp_wait0(); }
        __syncthreads();
        mma_chunk(c & 1);
        __syncthreads();
    }

    // epilogue: direct float2 stores with bias (+ELU)
    #pragma unroll
    for (int mt = 0; mt < MF; mt++)
        #pragma unroll
        for (int nt = 0; nt < NF; nt++) {
            int m = m0 + wm * WTM + mt * 16 + (lane >> 2);
            int n = n0 + wn * WTN + nt * 8 + (lane & 3) * 2;
            float b0 = bias[n], b1 = bias[n + 1];
            float2 v0, v1;
            v0.x = acc[mt][nt][0] + b0; v0.y = acc[mt][nt][1] + b1;
            v1.x = acc[mt][nt][2] + b0; v1.y = acc[mt][nt][3] + b1;
            if (ELU) {
                v0.x = (v0.x > 0.f) ? v0.x : expm1f(v0.x);
                v0.y = (v0.y > 0.f) ? v0.y : expm1f(v0.y);
                v1.x = (v1.x > 0.f) ? v1.x : expm1f(v1.x);
                v1.y = (v1.y > 0.f) ? v1.y : expm1f(v1.y);
            }
            *(float2*)&C[(size_t)m * N + n] = v0;
            *(float2*)&C[(size_t)(m + 8) * N + n] = v1;
        }
}

// ---------------- GRU gate + belief update (+ bf16 split of new belief) ----------------
__global__ void gate_k(float* __restrict__ out, int t) {
    int idx = blockIdx.x * blockDim.x + threadIdx.x;
    if (idx >= B * R) return;
    int b = idx / R, r = idx % R;
    size_t base = (size_t)b * N3;
    float ir = g_gi[base + r],          hr = g_gh[base + r];
    float iz = g_gi[base + R + r],      hz = g_gh[base + R + r];
    float in_ = g_gi[base + 2 * R + r], hn = g_gh[base + 2 * R + r];
    float rg = 1.f / (1.f + expf(-(ir + hr)));
    float zg = 1.f / (1.f + expf(-(iz + hz)));
    float ng = tanhf(in_ + rg * hn);
    float old = g_belief[idx];
    float nb = (1.f - zg) * ng + zg * old;
    g_belief[idx] = nb;
    __nv_bfloat16 h = __float2bfloat16(nb);
    g_bel_hi[idx] = h;
    g_bel_lo[idx] = __float2bfloat16(nb - __bfloat162float(h));
    size_t o = (size_t)b * T * R + (size_t)t * R + r;
    out[OFF_BEL + o]  = nb;
    out[OFF_PREV + o] = old;
}

// ---------------- epilogue ----------------
__global__ void epi_k(const float* __restrict__ noise,
                      const float* __restrict__ b_out,
                      float* __restrict__ out, int t) {
    int idx = blockIdx.x * blockDim.x + threadIdx.x;
    if (idx >= B * S) return;
    int b = idx / S, s = idx % S;
    float mean = b_out[s];
    float raw  = b_out[S + s];
    #pragma unroll
    for (int z = 0; z < SK; z++) {
        mean += g_msp[(size_t)z * B * NO + (size_t)b * NO + s];
        raw  += g_msp[(size_t)z * B * NO + (size_t)b * NO + S + s];
    }
    float sp  = fmaxf(raw, 0.f) + log1pf(expf(-fabsf(raw)));
    float std = sp + 0.1f;
    float eps = noise[(size_t)b * T * S + (size_t)t * S + s];
    float st  = fmaf(std, eps, mean);
    size_t o = (size_t)b * T * S + (size_t)t * S + s;
    out[OFF_MEAN + o]  = mean;
    out[OFF_STD + o]   = std;
    out[OFF_STATE + o] = st;
    g_state[idx] = st;
}

// ---------------- launch ----------------
extern "C" void kernel_launch(void* const* d_in, const int* in_sizes, int n_in,
                              void* d_out, int out_size) {
    const float* prior_state = (const float*)d_in[0];
    const float* belief0     = (const float*)d_in[1];
    const float* actions     = (const float*)d_in[2];
    const float* noise       = (const float*)d_in[3];
    const float* W_proj = (const float*)d_in[4];
    const float* b_proj = (const float*)d_in[5];
    const float* W_ih   = (const float*)d_in[6];
    const float* b_ih   = (const float*)d_in[7];
    const float* W_hh   = (const float*)d_in[8];
    const float* b_hh   = (const float*)d_in[9];
    const float* W_h1   = (const float*)d_in[10];
    const float* b_h1   = (const float*)d_in[11];
    const float* W_out  = (const float*)d_in[12];
    const float* b_out  = (const float*)d_in[13];
    float* out = (float*)d_out;

    float *p_xa, *p_gi, *p_gh, *p_h, *p_msp;
    __nv_bfloat16 *p_xh, *p_xl, *p_bh, *p_bl;
    __nv_bfloat16 *p_Wih_h, *p_Wih_l, *p_Whh_h, *p_Whh_l, *p_Wh1_h, *p_Wh1_l;
    cudaGetSymbolAddress((void**)&p_xa,  g_xa);
    cudaGetSymbolAddress((void**)&p_gi,  g_gi);
    cudaGetSymbolAddress((void**)&p_gh,  g_gh);
    cudaGetSymbolAddress((void**)&p_h,   g_h);
    cudaGetSymbolAddress((void**)&p_msp, g_msp);
    cudaGetSymbolAddress((void**)&p_xh,  g_x_hi);
    cudaGetSymbolAddress((void**)&p_xl,  g_x_lo);
    cudaGetSymbolAddress((void**)&p_bh,  g_bel_hi);
    cudaGetSymbolAddress((void**)&p_bl,  g_bel_lo);
    cudaGetSymbolAddress((void**)&p_Wih_h, g_Wih_hi);
    cudaGetSymbolAddress((void**)&p_Wih_l, g_Wih_lo);
    cudaGetSymbolAddress((void**)&p_Whh_h, g_Whh_hi);
    cudaGetSymbolAddress((void**)&p_Whh_l, g_Whh_lo);
    cudaGetSymbolAddress((void**)&p_Wh1_h, g_Wh1_hi);
    cudaGetSymbolAddress((void**)&p_Wh1_l, g_Wh1_lo);

    // dual gi/gh kernel: 128x128 tiles, 8 warps, 80KB dynamic smem
    constexpr uint32_t SMEM_DUAL = 2u * 2u * (128 + 128) * 80;  // 81920
    constexpr uint32_t SMEM_H1   = 2u * 2u * (64 + 64) * 80;    // 40960
    cudaFuncSetAttribute((const void*)mma_gemm<128, 128, 2, 4, 0, 1>,
                         cudaFuncAttributeMaxDynamicSharedMemorySize, SMEM_DUAL);
    cudaFuncSetAttribute((const void*)mma_gemm<64, 64, 2, 2, 1, 0>,
                         cudaFuncAttributeMaxDynamicSharedMemorySize, SMEM_H1);

    // one-time per replay: init recurrent state + weight transpose/split
    init_k<<<(B * R + 255) / 256, 256>>>(prior_state, belief0);
    prep_w<<<(N3 * H + 255) / 256, 256>>>(W_ih, p_Wih_h, p_Wih_l, H, N3);
    prep_w<<<(N3 * R + 255) / 256, 256>>>(W_hh, p_Whh_h, p_Whh_l, R, N3);
    prep_w<<<(H * R + 255) / 256, 256>>>(W_h1, p_Wh1_h, p_Wh1_l, R, H);

    for (int t = 0; t < T; t++) {
        // x_t = elu([state | action_t] @ W_proj + b_proj) -> bf16 hi/lo
        pack_k<<<(B * KP + 255) / 256, 256>>>(actions, t);
        gemm_k<64, 128, 16, 8, 8, /*EPI*/2, /*SK*/1>
            <<<dim3(H / 128, B / 64, 1), 128>>>(
                p_xa, W_proj, b_proj, (float*)p_xh, (float*)p_xl, B, H, KP);

        // gi = x @ W_ih + b_ih ; gh = belief @ W_hh + b_hh (tensor cores, dual via z)
        mma_gemm<128, 128, 2, 4, 0, 1>
            <<<dim3(N3 / 128, B / 128, 2), 256, SMEM_DUAL>>>(
                p_xh, p_xl, p_Wih_h, p_Wih_l, b_ih, p_gi,
                p_bh, p_bl, p_Whh_h, p_Whh_l, b_hh, p_gh, N3, H);

        // GRU gates -> new belief (+hi/lo), write beliefs + prev_beliefs
        gate_k<<<(B * R + 255) / 256, 256>>>(out, t);

        // h = elu(belief @ W_h1 + b_h1)  (tensor cores)
        mma_gemm<64, 64, 2, 2, 1, 0>
            <<<dim3(H / 64, B / 64, 1), 128, SMEM_H1>>>(
                p_bh, p_bl, p_Wh1_h, p_Wh1_l, b_h1, p_h,
                nullptr, nullptr, nullptr, nullptr, nullptr, nullptr, H, R);

        // [mean | raw_std] = h @ W_out (split-K partials)
        gemm_k<64, 64, 16, 8, 8, /*EPI*/3, /*SK*/SK>
            <<<dim3(NO / 64, B / 64, SK), 64>>>(
                p_h, W_out, nullptr, p_msp, nullptr, B, NO, R);

        epi_k<<<(B * S + 255) / 256, 256>>>(noise, b_out, out, t);
    }
}

// round 4
// speedup vs baseline: 2.3335x; 1.2575x over previous
#include <cuda_runtime.h>
#include <cuda_bf16.h>
#include <math.h>
#include <stdint.h>

// ---------------- problem constants ----------------
constexpr int B = 512, T = 64, S = 128, A = 32, H = 1024, R = 1024;
constexpr int KP = S + A;     // 160
constexpr int N3 = 3 * R;     // 3072
constexpr int NO = 2 * S;     // 256
constexpr int SK = 4;

constexpr size_t OFF_MEAN  = 0;
constexpr size_t OFF_STD   = OFF_MEAN  + (size_t)B * T * S;
constexpr size_t OFF_STATE = OFF_STD   + (size_t)B * T * S;
constexpr size_t OFF_BEL   = OFF_STATE + (size_t)B * T * S;
constexpr size_t OFF_PREV  = OFF_BEL   + (size_t)B * T * R;

// ---------------- device scratch ----------------
__device__ float g_gi[B * N3];
__device__ float g_gh[B * N3];
__device__ float g_belief[B * R];
__device__ float g_state [B * S];
__device__ float g_msp[SK * B * NO];

// bf16 split activations
__device__ __nv_bfloat16 g_xa_hi[B * KP], g_xa_lo[B * KP];
__device__ __nv_bfloat16 g_x_hi[B * H],   g_x_lo[B * H];
__device__ __nv_bfloat16 g_bel_hi[B * R], g_bel_lo[B * R];
__device__ __nv_bfloat16 g_h_hi[B * H],   g_h_lo[B * H];
// bf16 split transposed weights  [N][K]
__device__ __nv_bfloat16 g_Wpr_hi[H * KP], g_Wpr_lo[H * KP];
__device__ __nv_bfloat16 g_Wih_hi[N3 * H], g_Wih_lo[N3 * H];
__device__ __nv_bfloat16 g_Whh_hi[N3 * R], g_Whh_lo[N3 * R];
__device__ __nv_bfloat16 g_Wh1_hi[H * R],  g_Wh1_lo[H * R];
__device__ __nv_bfloat16 g_Wou_hi[NO * H], g_Wou_lo[NO * H];

// ---------------- portable PTX helpers (sm_80+ features only) ----------------
__device__ __forceinline__ uint32_t smem_to_u32(const void* p) {
    uint32_t a;
    asm("{ .reg .u64 t; cvta.to.shared.u64 t, %1; cvt.u32.u64 %0, t; }" : "=r"(a) : "l"(p));
    return a;
}
__device__ __forceinline__ void cp16(uint32_t saddr, const void* gaddr) {
    asm volatile("cp.async.cg.shared.global [%0], [%1], 16;" :: "r"(saddr), "l"(gaddr) : "memory");
}
__device__ __forceinline__ void cp_commit() { asm volatile("cp.async.commit_group;" ::: "memory"); }
__device__ __forceinline__ void cp_wait1()  { asm volatile("cp.async.wait_group 1;" ::: "memory"); }

__device__ __forceinline__ void ldsm4(uint32_t a, uint32_t& r0, uint32_t& r1,
                                      uint32_t& r2, uint32_t& r3) {
    asm volatile("ldmatrix.sync.aligned.m8n8.x4.shared.b16 {%0,%1,%2,%3}, [%4];"
                 : "=r"(r0), "=r"(r1), "=r"(r2), "=r"(r3) : "r"(a));
}
__device__ __forceinline__ void mma_bf16(float* c, const uint32_t* a, const uint32_t* b) {
    asm volatile("mma.sync.aligned.m16n8k16.row.col.f32.bf16.bf16.f32 "
                 "{%0,%1,%2,%3},{%4,%5,%6,%7},{%8,%9},{%0,%1,%2,%3};"
                 : "+f"(c[0]), "+f"(c[1]), "+f"(c[2]), "+f"(c[3])
                 : "r"(a[0]), "r"(a[1]), "r"(a[2]), "r"(a[3]), "r"(b[0]), "r"(b[1]));
}
__device__ __forceinline__ float elu1(float v) { return (v > 0.f) ? v : expm1f(v); }

// ---------------- init ----------------
__global__ void init_k(const float* __restrict__ prior_state,
                       const float* __restrict__ belief0) {
    int idx = blockIdx.x * blockDim.x + threadIdx.x;
    if (idx < B * R) {
        float v = belief0[idx];
        g_belief[idx] = v;
        __nv_bfloat16 h = __float2bfloat16(v);
        g_bel_hi[idx] = h;
        g_bel_lo[idx] = __float2bfloat16(v - __bfloat162float(h));
    }
    if (idx < B * S) g_state[idx] = prior_state[idx];
}

// ---------------- weight prep: W[K][N] -> hi/lo[N][K] ----------------
__global__ void prep_w(const float* __restrict__ W, __nv_bfloat16* __restrict__ hi,
                       __nv_bfloat16* __restrict__ lo, int K, int N) {
    int idx = blockIdx.x * blockDim.x + threadIdx.x;
    if (idx >= N * K) return;
    int n = idx / K, k = idx % K;
    float v = W[(size_t)k * N + n];
    __nv_bfloat16 h = __float2bfloat16(v);
    hi[idx] = h;
    lo[idx] = __float2bfloat16(v - __bfloat162float(h));
}

// ---------------- pack: xa = [state | action_t] as bf16 hi/lo ----------------
__global__ void pack_k(const float* __restrict__ actions, int t) {
    int idx = blockIdx.x * blockDim.x + threadIdx.x;
    if (idx >= B * KP) return;
    int b = idx / KP, j = idx % KP;
    float v = (j < S) ? g_state[b * S + j]
                      : actions[(size_t)b * T * A + (size_t)t * A + (j - S)];
    __nv_bfloat16 h = __float2bfloat16(v);
    g_xa_hi[idx] = h;
    g_xa_lo[idx] = __float2bfloat16(v - __bfloat162float(h));
}

// ---------------- bf16-split tensor-core GEMM, 3-stage cp.async pipeline -----
// C[M, N] = A[M, K] @ B[N, K]^T, 3-pass hi/lo split, fp32 accum.
// EPI: 0 = store acc+bias fp32 (DUAL selects set via blockIdx.z)
//      2 = elu(acc+bias) -> bf16 hi/lo split store
//      3 = split-K partial fp32 store (SPLITK slices via blockIdx.z)
template<int BM, int BN, int WRM, int WRN, int EPI, int DUAL, int SPLITK>
__global__ void __launch_bounds__(WRM * WRN * 32)
mma_gemm(const __nv_bfloat16* __restrict__ Ahi0, const __nv_bfloat16* __restrict__ Alo0,
         const __nv_bfloat16* __restrict__ Bhi0, const __nv_bfloat16* __restrict__ Blo0,
         const float* __restrict__ bias0, float* __restrict__ Cf0,
         __nv_bfloat16* __restrict__ Chi, __nv_bfloat16* __restrict__ Clo,
         const __nv_bfloat16* __restrict__ Ahi1, const __nv_bfloat16* __restrict__ Alo1,
         const __nv_bfloat16* __restrict__ Bhi1, const __nv_bfloat16* __restrict__ Blo1,
         const float* __restrict__ bias1, float* __restrict__ Cf1,
         int M, int N, int K) {
    constexpr int THREADS = WRM * WRN * 32;
    constexpr int WTM = BM / WRM, WTN = BN / WRN;
    constexpr int MF = WTM / 16, NF = WTN / 8;
    constexpr int RS = 80;                         // smem row stride (bytes)
    constexpr uint32_t OFS_AH = 0;
    constexpr uint32_t OFS_AL = (uint32_t)BM * RS;
    constexpr uint32_t OFS_BH = 2u * BM * RS;
    constexpr uint32_t OFS_BL = 2u * BM * RS + (uint32_t)BN * RS;
    constexpr uint32_t BUFSZ  = 2u * (BM + BN) * RS;
    constexpr int PPT = (BM + BN) * 8 / THREADS;   // cp.async pieces per thread

    extern __shared__ char smem[];
    const uint32_t sb = smem_to_u32(smem);

    const int tid = threadIdx.x;
    const int wid = tid >> 5, lane = tid & 31;
    const int wm = wid / WRN, wn = wid % WRN;
    const int m0 = blockIdx.y * BM, n0 = blockIdx.x * BN;

    const __nv_bfloat16 *Ahi = Ahi0, *Alo = Alo0, *Bhi = Bhi0, *Blo = Blo0;
    const float* bias = bias0;
    float* Cf = Cf0;
    if (DUAL && blockIdx.z == 1) { Ahi = Ahi1; Alo = Alo1; Bhi = Bhi1; Blo = Blo1; bias = bias1; Cf = Cf1; }

    int kz0 = 0, KS = K;
    if (SPLITK > 1) { KS = K / SPLITK; kz0 = blockIdx.z * KS; }
    const int NC = KS / 32;

    const __nv_bfloat16* s0 = Ahi + (size_t)m0 * K + kz0;
    const __nv_bfloat16* s1 = Alo + (size_t)m0 * K + kz0;
    const __nv_bfloat16* s2 = Bhi + (size_t)n0 * K + kz0;
    const __nv_bfloat16* s3 = Blo + (size_t)n0 * K + kz0;

    float acc[MF][NF][4];
    #pragma unroll
    for (int i = 0; i < MF; i++)
        #pragma unroll
        for (int j = 0; j < NF; j++)
            #pragma unroll
            for (int q = 0; q < 4; q++) acc[i][j][q] = 0.f;

    auto load_chunk = [&](int c, int buf) {
        uint32_t base = sb + (uint32_t)buf * BUFSZ;
        #pragma unroll
        for (int i = 0; i < PPT; i++) {
            int p = tid + i * THREADS;
            const __nv_bfloat16* s;
            uint32_t ofs;
            int local;
            if (p < BM * 4)                   { s = s0; ofs = OFS_AH; local = p; }
            else if (p < 2 * BM * 4)          { s = s1; ofs = OFS_AL; local = p - BM * 4; }
            else if (p < 2 * BM * 4 + BN * 4) { s = s2; ofs = OFS_BH; local = p - 2 * BM * 4; }
            else                              { s = s3; ofs = OFS_BL; local = p - 2 * BM * 4 - BN * 4; }
            int row = local >> 2, k16 = local & 3;
            cp16(base + ofs + (uint32_t)row * RS + (uint32_t)k16 * 16,
                 s + (size_t)row * K + c * 32 + k16 * 8);
        }
    };

    auto mma_chunk = [&](int buf) {
        uint32_t base = sb + (uint32_t)buf * BUFSZ;
        const int grp = lane >> 3, l8 = lane & 7;
        #pragma unroll
        for (int ks = 0; ks < 2; ks++) {
            uint32_t ahi[MF][4], alo[MF][4], bhi[NF][2], blo[NF][2];
            uint32_t arow = (uint32_t)(wm * WTM + (grp & 1) * 8 + l8);
            uint32_t acol = (uint32_t)(ks * 32 + (grp >> 1) * 16);
            #pragma unroll
            for (int mt = 0; mt < MF; mt++) {
                uint32_t r = (arow + mt * 16) * RS + acol;
                ldsm4(base + OFS_AH + r, ahi[mt][0], ahi[mt][1], ahi[mt][2], ahi[mt][3]);
                ldsm4(base + OFS_AL + r, alo[mt][0], alo[mt][1], alo[mt][2], alo[mt][3]);
            }
            uint32_t brow = (uint32_t)(wn * WTN + (grp >> 1) * 8 + l8);
            uint32_t bcol = (uint32_t)(ks * 32 + (grp & 1) * 16);
            #pragma unroll
            for (int np = 0; np < NF / 2; np++) {
                uint32_t r = (brow + np * 16) * RS + bcol;
                ldsm4(base + OFS_BH + r, bhi[2 * np][0], bhi[2 * np][1],
                      bhi[2 * np + 1][0], bhi[2 * np + 1][1]);
                ldsm4(base + OFS_BL + r, blo[2 * np][0], blo[2 * np][1],
                      blo[2 * np + 1][0], blo[2 * np + 1][1]);
            }
            #pragma unroll
            for (int mt = 0; mt < MF; mt++)
                #pragma unroll
                for (int nt = 0; nt < NF; nt++) {
                    mma_bf16(acc[mt][nt], ahi[mt], bhi[nt]);
                    mma_bf16(acc[mt][nt], ahi[mt], blo[nt]);
                    mma_bf16(acc[mt][nt], alo[mt], bhi[nt]);
                }
        }
    };

    // 3-stage pipeline: chunks c and c+1 in flight, one sync per chunk
    load_chunk(0, 0); cp_commit();
    if (NC > 1) load_chunk(1, 1);
    cp_commit();
    for (int c = 0; c < NC; c++) {
        cp_wait1();
        __syncthreads();
        mma_chunk(c % 3);
        if (c + 2 < NC) load_chunk(c + 2, (c + 2) % 3);
        cp_commit();
    }

    // ---- epilogue ----
    #pragma unroll
    for (int mt = 0; mt < MF; mt++)
        #pragma unroll
        for (int nt = 0; nt < NF; nt++) {
            int m = m0 + wm * WTM + mt * 16 + (lane >> 2);
            int n = n0 + wn * WTN + nt * 8 + (lane & 3) * 2;
            if constexpr (EPI == 3) {
                float* Cz = Cf + (size_t)blockIdx.z * M * N;
                float2 v0 = make_float2(acc[mt][nt][0], acc[mt][nt][1]);
                float2 v1 = make_float2(acc[mt][nt][2], acc[mt][nt][3]);
                *(float2*)&Cz[(size_t)m * N + n] = v0;
                *(float2*)&Cz[(size_t)(m + 8) * N + n] = v1;
            } else if constexpr (EPI == 2) {
                float b0 = bias[n], b1 = bias[n + 1];
                float v00 = elu1(acc[mt][nt][0] + b0), v01 = elu1(acc[mt][nt][1] + b1);
                float v10 = elu1(acc[mt][nt][2] + b0), v11 = elu1(acc[mt][nt][3] + b1);
                __nv_bfloat16 h00 = __float2bfloat16(v00), h01 = __float2bfloat16(v01);
                __nv_bfloat16 h10 = __float2bfloat16(v10), h11 = __float2bfloat16(v11);
                __nv_bfloat162 hi0; hi0.x = h00; hi0.y = h01;
                __nv_bfloat162 hi1; hi1.x = h10; hi1.y = h11;
                __nv_bfloat162 lo0, lo1;
                lo0.x = __float2bfloat16(v00 - __bfloat162float(h00));
                lo0.y = __float2bfloat16(v01 - __bfloat162float(h01));
                lo1.x = __float2bfloat16(v10 - __bfloat162float(h10));
                lo1.y = __float2bfloat16(v11 - __bfloat162float(h11));
                *(__nv_bfloat162*)&Chi[(size_t)m * N + n] = hi0;
                *(__nv_bfloat162*)&Clo[(size_t)m * N + n] = lo0;
                *(__nv_bfloat162*)&Chi[(size_t)(m + 8) * N + n] = hi1;
                *(__nv_bfloat162*)&Clo[(size_t)(m + 8) * N + n] = lo1;
            } else {
                float b0 = bias[n], b1 = bias[n + 1];
                float2 v0 = make_float2(acc[mt][nt][0] + b0, acc[mt][nt][1] + b1);
                float2 v1 = make_float2(acc[mt][nt][2] + b0, acc[mt][nt][3] + b1);
                *(float2*)&Cf[(size_t)m * N + n] = v0;
                *(float2*)&Cf[(size_t)(m + 8) * N + n] = v1;
            }
        }
}

// ---------------- GRU gate + belief update (+ bf16 split of new belief) -----
__global__ void gate_k(float* __restrict__ out, int t) {
    int idx = blockIdx.x * blockDim.x + threadIdx.x;
    if (idx >= B * R) return;
    int b = idx / R, r = idx % R;
    size_t base = (size_t)b * N3;
    float ir = g_gi[base + r],          hr = g_gh[base + r];
    float iz = g_gi[base + R + r],      hz = g_gh[base + R + r];
    float in_ = g_gi[base + 2 * R + r], hn = g_gh[base + 2 * R + r];
    float rg = 1.f / (1.f + expf(-(ir + hr)));
    float zg = 1.f / (1.f + expf(-(iz + hz)));
    float ng = tanhf(in_ + rg * hn);
    float old = g_belief[idx];
    float nb = (1.f - zg) * ng + zg * old;
    g_belief[idx] = nb;
    __nv_bfloat16 h = __float2bfloat16(nb);
    g_bel_hi[idx] = h;
    g_bel_lo[idx] = __float2bfloat16(nb - __bfloat162float(h));
    size_t o = (size_t)b * T * R + (size_t)t * R + r;
    out[OFF_BEL + o]  = nb;
    out[OFF_PREV + o] = old;
}

// ---------------- epilogue: reduce split-K, softplus, sample ----------------
__global__ void epi_k(const float* __restrict__ noise,
                      const float* __restrict__ b_out,
                      float* __restrict__ out, int t) {
    int idx = blockIdx.x * blockDim.x + threadIdx.x;
    if (idx >= B * S) return;
    int b = idx / S, s = idx % S;
    float mean = b_out[s];
    float raw  = b_out[S + s];
    #pragma unroll
    for (int z = 0; z < SK; z++) {
        mean += g_msp[(size_t)z * B * NO + (size_t)b * NO + s];
        raw  += g_msp[(size_t)z * B * NO + (size_t)b * NO + S + s];
    }
    float sp  = fmaxf(raw, 0.f) + log1pf(expf(-fabsf(raw)));
    float std = sp + 0.1f;
    float eps = noise[(size_t)b * T * S + (size_t)t * S + s];
    float st  = fmaf(std, eps, mean);
    size_t o = (size_t)b * T * S + (size_t)t * S + s;
    out[OFF_MEAN + o]  = mean;
    out[OFF_STD + o]   = std;
    out[OFF_STATE + o] = st;
    g_state[idx] = st;
}

// ---------------- launch ----------------
extern "C" void kernel_launch(void* const* d_in, const int* in_sizes, int n_in,
                              void* d_out, int out_size) {
    const float* prior_state = (const float*)d_in[0];
    const float* belief0     = (const float*)d_in[1];
    const float* actions     = (const float*)d_in[2];
    const float* noise       = (const float*)d_in[3];
    const float* W_proj = (const float*)d_in[4];
    const float* b_proj = (const float*)d_in[5];
    const float* W_ih   = (const float*)d_in[6];
    const float* b_ih   = (const float*)d_in[7];
    const float* W_hh   = (const float*)d_in[8];
    const float* b_hh   = (const float*)d_in[9];
    const float* W_h1   = (const float*)d_in[10];
    const float* b_h1   = (const float*)d_in[11];
    const float* W_out  = (const float*)d_in[12];
    const float* b_out  = (const float*)d_in[13];
    float* out = (float*)d_out;

    float *p_gi, *p_gh, *p_msp;
    __nv_bfloat16 *p_xah, *p_xal, *p_xh, *p_xl, *p_bh, *p_bl, *p_hh, *p_hl;
    __nv_bfloat16 *p_Wpr_h, *p_Wpr_l, *p_Wih_h, *p_Wih_l, *p_Whh_h, *p_Whh_l;
    __nv_bfloat16 *p_Wh1_h, *p_Wh1_l, *p_Wou_h, *p_Wou_l;
    cudaGetSymbolAddress((void**)&p_gi,  g_gi);
    cudaGetSymbolAddress((void**)&p_gh,  g_gh);
    cudaGetSymbolAddress((void**)&p_msp, g_msp);
    cudaGetSymbolAddress((void**)&p_xah, g_xa_hi);
    cudaGetSymbolAddress((void**)&p_xal, g_xa_lo);
    cudaGetSymbolAddress((void**)&p_xh,  g_x_hi);
    cudaGetSymbolAddress((void**)&p_xl,  g_x_lo);
    cudaGetSymbolAddress((void**)&p_bh,  g_bel_hi);
    cudaGetSymbolAddress((void**)&p_bl,  g_bel_lo);
    cudaGetSymbolAddress((void**)&p_hh,  g_h_hi);
    cudaGetSymbolAddress((void**)&p_hl,  g_h_lo);
    cudaGetSymbolAddress((void**)&p_Wpr_h, g_Wpr_hi);
    cudaGetSymbolAddress((void**)&p_Wpr_l, g_Wpr_lo);
    cudaGetSymbolAddress((void**)&p_Wih_h, g_Wih_hi);
    cudaGetSymbolAddress((void**)&p_Wih_l, g_Wih_lo);
    cudaGetSymbolAddress((void**)&p_Whh_h, g_Whh_hi);
    cudaGetSymbolAddress((void**)&p_Whh_l, g_Whh_lo);
    cudaGetSymbolAddress((void**)&p_Wh1_h, g_Wh1_hi);
    cudaGetSymbolAddress((void**)&p_Wh1_l, g_Wh1_lo);
    cudaGetSymbolAddress((void**)&p_Wou_h, g_Wou_hi);
    cudaGetSymbolAddress((void**)&p_Wou_l, g_Wou_lo);

    constexpr uint32_t SMEM_BIG = 3u * 2u * (128 + 128) * 80;  // 122880
    constexpr uint32_t SMEM_SML = 3u * 2u * (64 + 64) * 80;    // 61440
    cudaFuncSetAttribute((const void*)mma_gemm<128, 128, 2, 4, 0, 1, 1>,
                         cudaFuncAttributeMaxDynamicSharedMemorySize, SMEM_BIG);
    cudaFuncSetAttribute((const void*)mma_gemm<64, 64, 2, 2, 2, 0, 1>,
                         cudaFuncAttributeMaxDynamicSharedMemorySize, SMEM_SML);
    cudaFuncSetAttribute((const void*)mma_gemm<64, 64, 2, 2, 3, 0, SK>,
                         cudaFuncAttributeMaxDynamicSharedMemorySize, SMEM_SML);

    // one-time per replay: init recurrent state + weight transpose/split
    init_k<<<(B * R + 255) / 256, 256>>>(prior_state, belief0);
    prep_w<<<(H * KP + 255) / 256, 256>>>(W_proj, p_Wpr_h, p_Wpr_l, KP, H);
    prep_w<<<(N3 * H + 255) / 256, 256>>>(W_ih, p_Wih_h, p_Wih_l, H, N3);
    prep_w<<<(N3 * R + 255) / 256, 256>>>(W_hh, p_Whh_h, p_Whh_l, R, N3);
    prep_w<<<(H * R + 255) / 256, 256>>>(W_h1, p_Wh1_h, p_Wh1_l, R, H);
    prep_w<<<(NO * H + 255) / 256, 256>>>(W_out, p_Wou_h, p_Wou_l, H, NO);

    for (int t = 0; t < T; t++) {
        // xa = [state | action_t] -> bf16 hi/lo
        pack_k<<<(B * KP + 255) / 256, 256>>>(actions, t);

        // x = elu(xa @ W_proj + b_proj) -> bf16 hi/lo   (tensor cores, K=160)
        mma_gemm<64, 64, 2, 2, 2, 0, 1>
            <<<dim3(H / 64, B / 64, 1), 128, SMEM_SML>>>(
                p_xah, p_xal, p_Wpr_h, p_Wpr_l, b_proj, nullptr, p_xh, p_xl,
                nullptr, nullptr, nullptr, nullptr, nullptr, nullptr, B, H, KP);

        // gi = x @ W_ih + b_ih ; gh = belief @ W_hh + b_hh (dual via z)
        mma_gemm<128, 128, 2, 4, 0, 1, 1>
            <<<dim3(N3 / 128, B / 128, 2), 256, SMEM_BIG>>>(
                p_xh, p_xl, p_Wih_h, p_Wih_l, b_ih, p_gi, nullptr, nullptr,
                p_bh, p_bl, p_Whh_h, p_Whh_l, b_hh, p_gh, B, N3, H);

        // GRU gates -> new belief (+hi/lo), write beliefs + prev_beliefs
        gate_k<<<(B * R + 255) / 256, 256>>>(out, t);

        // h = elu(belief @ W_h1 + b_h1) -> bf16 hi/lo
        mma_gemm<64, 64, 2, 2, 2, 0, 1>
            <<<dim3(H / 64, B / 64, 1), 128, SMEM_SML>>>(
                p_bh, p_bl, p_Wh1_h, p_Wh1_l, b_h1, nullptr, p_hh, p_hl,
                nullptr, nullptr, nullptr, nullptr, nullptr, nullptr, B, H, R);

        // [mean | raw_std] = h @ W_out  (split-K=4 partials, tensor cores)
        mma_gemm<64, 64, 2, 2, 3, 0, SK>
            <<<dim3(NO / 64, B / 64, SK), 128, SMEM_SML>>>(
                p_hh, p_hl, p_Wou_h, p_Wou_l, nullptr, p_msp, nullptr, nullptr,
                nullptr, nullptr, nullptr, nullptr, nullptr, nullptr, B, NO, H);

        // reduce partials + bias, softplus, reparam sample
        epi_k<<<(B * S + 255) / 256, 256>>>(noise, b_out, out, t);
    }
}